// round 2
// baseline (speedup 1.0000x reference)
#include <cuda_runtime.h>
#include <math_constants.h>

#define SEQ 1024
#define BSZ 8
#define EMBED 512
#define NH 8
#define QHD 32
#define PD 4
#define IN_PROJ 544

// Scratch for projected q/k/p, laid out [b][h][s][d] so kernel 2 streams contiguously.
__device__ float g_Q[BSZ * NH * SEQ * QHD];   // 8 MB
__device__ float g_K[BSZ * NH * SEQ * QHD];   // 8 MB
__device__ float g_P[BSZ * NH * SEQ * PD];    // 1 MB

// ---------------- packed f32x2 helpers (Blackwell FFMA2 path) ----------------
__device__ __forceinline__ void fma2(unsigned long long& d,
                                     unsigned long long a,
                                     unsigned long long b) {
    asm("fma.rn.f32x2 %0, %1, %2, %0;" : "+l"(d) : "l"(a), "l"(b));
}
__device__ __forceinline__ unsigned long long pk2(float lo, float hi) {
    unsigned long long r;
    asm("mov.b64 %0, {%1, %2};" : "=l"(r) : "f"(lo), "f"(hi));
    return r;
}
__device__ __forceinline__ float fold2(unsigned long long v) {
    float lo, hi;
    asm("mov.b64 {%0, %1}, %2;" : "=f"(lo), "=f"(hi) : "l"(v));
    return lo + hi;
}

// ---------------------------------------------------------------------------
// Kernel 1: xp = x @ W^T + b, scattered into g_Q / g_K / g_P.
// Tiles 128m x 64n, BK=16, 256 threads, 8m x 4n per thread, f32x2 along m.
// ---------------------------------------------------------------------------
#define PM 132   // As row pitch (floats), 528B = 16B-aligned rows
#define PN 68    // Bs row pitch

__global__ __launch_bounds__(256) void proj_kernel(
    const float* __restrict__ x, const float* __restrict__ W,
    const float* __restrict__ bias)
{
    __shared__ float As[16 * PM];   // [k][m]
    __shared__ float Bs[16 * PN];   // [k][n]

    const int tid = threadIdx.x;
    const int n0 = blockIdx.x * 64;
    const int m0 = blockIdx.y * 128;
    const int tx = tid & 15;        // n-group: 4 cols
    const int ty = tid >> 4;        // m-group: 8 rows (4 pairs)

    unsigned long long acc[4][4];   // [m-pair][n]
#pragma unroll
    for (int i = 0; i < 4; i++)
#pragma unroll
        for (int j = 0; j < 4; j++) acc[i][j] = 0ull;

    // staging indices
    const int am = tid >> 1;              // 0..127
    const int ak = (tid & 1) * 8;         // 0 or 8
    const int bn = tid >> 2;              // 0..63
    const int bk = (tid & 3) * 4;         // 0,4,8,12

    for (int k0 = 0; k0 < EMBED; k0 += 16) {
        // stage A: 128x16 (two float4 per thread), transpose into As[k][m]
#pragma unroll
        for (int i = 0; i < 2; i++) {
            float4 v = *(const float4*)&x[(size_t)(m0 + am) * EMBED + k0 + ak + i * 4];
            As[(ak + i * 4 + 0) * PM + am] = v.x;
            As[(ak + i * 4 + 1) * PM + am] = v.y;
            As[(ak + i * 4 + 2) * PM + am] = v.z;
            As[(ak + i * 4 + 3) * PM + am] = v.w;
        }
        // stage B: 64x16 (one float4 per thread), transpose into Bs[k][n]
        {
            float4 v = make_float4(0.f, 0.f, 0.f, 0.f);
            if (n0 + bn < IN_PROJ)
                v = *(const float4*)&W[(size_t)(n0 + bn) * EMBED + k0 + bk];
            Bs[(bk + 0) * PN + bn] = v.x;
            Bs[(bk + 1) * PN + bn] = v.y;
            Bs[(bk + 2) * PN + bn] = v.z;
            Bs[(bk + 3) * PN + bn] = v.w;
        }
        __syncthreads();

#pragma unroll
        for (int k = 0; k < 16; k++) {
            ulonglong2 a01 = *(const ulonglong2*)&As[k * PM + ty * 8];
            ulonglong2 a23 = *(const ulonglong2*)&As[k * PM + ty * 8 + 4];
            float4 b4 = *(const float4*)&Bs[k * PN + tx * 4];
            unsigned long long bd[4];
            bd[0] = pk2(b4.x, b4.x); bd[1] = pk2(b4.y, b4.y);
            bd[2] = pk2(b4.z, b4.z); bd[3] = pk2(b4.w, b4.w);
#pragma unroll
            for (int j = 0; j < 4; j++) {
                fma2(acc[0][j], a01.x, bd[j]);
                fma2(acc[1][j], a01.y, bd[j]);
                fma2(acc[2][j], a23.x, bd[j]);
                fma2(acc[3][j], a23.y, bd[j]);
            }
        }
        __syncthreads();
    }

#pragma unroll
    for (int j = 0; j < 4; j++) {
        const int n = n0 + tx * 4 + j;
        if (n >= IN_PROJ) continue;
        const float bv = bias[n];
#pragma unroll
        for (int i = 0; i < 4; i++) {
            float lo, hi;
            asm("mov.b64 {%0, %1}, %2;" : "=f"(lo), "=f"(hi) : "l"(acc[i][j]));
#pragma unroll
            for (int half = 0; half < 2; half++) {
                const float v = (half ? hi : lo) + bv;
                const int m = m0 + ty * 8 + i * 2 + half;
                const int s = m >> 3;
                const int bb = m & 7;
                if (n < 256) {
                    const int h = n >> 5, d = n & 31;
                    g_Q[(((size_t)(bb * NH + h)) * SEQ + s) * QHD + d] = v;
                } else if (n < 512) {
                    const int g = n - 256;
                    const int h = g >> 5, d = g & 31;
                    g_K[(((size_t)(bb * NH + h)) * SEQ + s) * QHD + d] = v;
                } else {
                    const int g = n - 512;
                    const int h = g >> 2, d = g & 3;
                    g_P[(((size_t)(bb * NH + h)) * SEQ + s) * PD + d] = v;
                }
            }
        }
    }
}

// ---------------------------------------------------------------------------
// Kernel 2: per (b, h, 32-row t-tile): scores = QK^T + pos + offset over full
// s=1024 in SMEM, row softmax, single write. 512 threads, 8t x 4s reg tiles,
// packed f32x2 FMA, SC=512 K chunks.
// ---------------------------------------------------------------------------
#define TT 32
#define SC 512
#define KPITCH 36                                 // floats per K row (8 f4 + pad)
#define KS_OFF (TT * SEQ)                         // 32768
#define QS_OFF (KS_OFF + SC * KPITCH)             // 32768 + 18432 = 51200
#define PS_OFF (QS_OFF + TT * QHD)                // 52224
#define SMEM_FLOATS (PS_OFF + TT * PD)            // 52352 -> 209408 bytes

__global__ __launch_bounds__(512) void attn_kernel(
    const float* __restrict__ pos, const float* __restrict__ off,
    float* __restrict__ out)
{
    extern __shared__ float sm[];
    float* sc = sm;                       // [TT][SEQ]
    float* Ks = sm + KS_OFF;              // [SC][KPITCH]
    float* Qs = sm + QS_OFF;              // [TT][QHD]
    float* Ps = sm + PS_OFF;              // [TT][PD]

    const int tid = threadIdx.x;
    const int t0 = blockIdx.x * TT;
    const int h = blockIdx.y;
    const int b = blockIdx.z;

    const float* Qg = g_Q + ((size_t)(b * NH + h)) * SEQ * QHD;
    const float* Kg = g_K + ((size_t)(b * NH + h)) * SEQ * QHD;
    const float* Pg = g_P + ((size_t)(b * NH + h)) * SEQ * PD;

    // Stage Q tile and P vectors once.
    if (tid < 256) {
        const int r = tid >> 3, d4 = tid & 7;
        *(float4*)&Qs[r * QHD + d4 * 4] =
            *(const float4*)&Qg[(size_t)(t0 + r) * QHD + d4 * 4];
    }
    if (tid < TT)
        *(float4*)&Ps[tid * PD] = *(const float4*)&Pg[(size_t)(t0 + tid) * PD];

    const int cl = tid & 127;    // s lane: covers s = s0 + cl + j*128
    const int tg = tid >> 7;     // 0..3 -> rows tg*8 .. tg*8+7
    const float* qrow = Qs + (tg * 8) * QHD;

    for (int s0 = 0; s0 < SEQ; s0 += SC) {
        __syncthreads();   // K buffer reuse (and Q/P staging on first iter)
        // stage K chunk: SC x 8 float4, 8 per thread, coalesced
#pragma unroll
        for (int i = 0; i < (SC * 8) / 512; i++) {
            const int idx = tid + i * 512;
            const int s = idx >> 3, d4 = idx & 7;
            *(float4*)&Ks[s * KPITCH + d4 * 4] =
                *(const float4*)&Kg[(size_t)(s0 + s) * QHD + d4 * 4];
        }
        __syncthreads();

        // two j-groups of 2 s-values each (keeps regs under control)
#pragma unroll
        for (int jp = 0; jp < 2; jp++) {
            unsigned long long acc[8][2];
#pragma unroll
            for (int r = 0; r < 8; r++) { acc[r][0] = 0ull; acc[r][1] = 0ull; }

#pragma unroll
            for (int d4 = 0; d4 < 8; d4++) {
                ulonglong2 q2[8];
#pragma unroll
                for (int r = 0; r < 8; r++)
                    q2[r] = *(const ulonglong2*)&qrow[r * QHD + d4 * 4];
#pragma unroll
                for (int jj = 0; jj < 2; jj++) {
                    const int s_l = cl + (jp * 2 + jj) * 128;
                    ulonglong2 k2 = *(const ulonglong2*)&Ks[s_l * KPITCH + d4 * 4];
#pragma unroll
                    for (int r = 0; r < 8; r++) {
                        fma2(acc[r][jj], q2[r].x, k2.x);
                        fma2(acc[r][jj], q2[r].y, k2.y);
                    }
                }
            }

            // epilogue: + pos + offset, store to score tile
#pragma unroll
            for (int jj = 0; jj < 2; jj++) {
                const int s = s0 + cl + (jp * 2 + jj) * 128;
#pragma unroll
                for (int r = 0; r < 8; r++) {
                    const int t = tg * 8 + r;
                    const int tglob = t0 + t;
                    const float4 p = *(const float4*)&Ps[t * PD];
                    const float4 pe = *(const float4*)&pos[((size_t)tglob * SEQ + s) * PD];
                    const float o = off[((size_t)b * SEQ + tglob) * SEQ + s];
                    sc[t * SEQ + s] = fold2(acc[r][jj]) +
                        p.x * pe.x + p.y * pe.y + p.z * pe.z + p.w * pe.w + o;
                }
            }
        }
    }
    __syncthreads();

    // Row softmax: 16 warps, warp w owns rows 2w, 2w+1.
    const int warp = tid >> 5, lane = tid & 31;
#pragma unroll
    for (int rr = 0; rr < 2; rr++) {
        const int t = warp * 2 + rr;
        float4* row = (float4*)&sc[t * SEQ];   // 256 float4

        float m = -CUDART_INF_F;
#pragma unroll
        for (int k = 0; k < 8; k++) {
            const float4 v = row[lane + 32 * k];
            m = fmaxf(m, fmaxf(fmaxf(v.x, v.y), fmaxf(v.z, v.w)));
        }
#pragma unroll
        for (int o_ = 16; o_ > 0; o_ >>= 1)
            m = fmaxf(m, __shfl_xor_sync(0xffffffffu, m, o_));

        float sum = 0.f;
#pragma unroll
        for (int k = 0; k < 8; k++) {
            float4 v = row[lane + 32 * k];
            v.x = __expf(v.x - m); v.y = __expf(v.y - m);
            v.z = __expf(v.z - m); v.w = __expf(v.w - m);
            row[lane + 32 * k] = v;
            sum += v.x + v.y + v.z + v.w;
        }
#pragma unroll
        for (int o_ = 16; o_ > 0; o_ >>= 1)
            sum += __shfl_xor_sync(0xffffffffu, sum, o_);
        const float inv = 1.0f / sum;

        float4* orow = (float4*)&out[(((size_t)h * BSZ + b) * SEQ + (t0 + t)) * SEQ];
#pragma unroll
        for (int k = 0; k < 8; k++) {
            float4 v = row[lane + 32 * k];
            v.x *= inv; v.y *= inv; v.z *= inv; v.w *= inv;
            orow[lane + 32 * k] = v;
        }
    }
}

// ---------------------------------------------------------------------------
extern "C" void kernel_launch(void* const* d_in, const int* in_sizes, int n_in,
                              void* d_out, int out_size)
{
    const float* x    = (const float*)d_in[0];
    const float* pos  = (const float*)d_in[1];
    const float* off  = (const float*)d_in[2];
    const float* W    = (const float*)d_in[3];
    const float* bias = (const float*)d_in[4];
    float* out = (float*)d_out;

    cudaFuncSetAttribute(attn_kernel, cudaFuncAttributeMaxDynamicSharedMemorySize,
                         SMEM_FLOATS * (int)sizeof(float));

    dim3 gproj((IN_PROJ + 63) / 64, (SEQ * BSZ) / 128);   // 9 x 64
    proj_kernel<<<gproj, 256>>>(x, W, bias);

    dim3 gattn(SEQ / TT, NH, BSZ);                         // 32 x 8 x 8
    attn_kernel<<<gattn, 512, SMEM_FLOATS * (int)sizeof(float)>>>(pos, off, out);
}

// round 3
// speedup vs baseline: 4.8055x; 4.8055x over previous
#include <cuda_runtime.h>
#include <math_constants.h>

#define SEQ 1024
#define BSZ 8
#define EMBED 512
#define NH 8
#define QHD 32
#define PD 4
#define IN_PROJ 544

// Scratch for projected q/k/p, laid out [b][h][s][d] so kernel 2 streams contiguously.
__device__ float g_Q[BSZ * NH * SEQ * QHD];   // 8 MB
__device__ float g_K[BSZ * NH * SEQ * QHD];   // 8 MB
__device__ float g_P[BSZ * NH * SEQ * PD];    // 1 MB

// ---------------------------------------------------------------------------
// Kernel 1: xp = x @ W^T + b, scattered into g_Q / g_K / g_P.
// (Round-1 version, measured ~150us — at scalar FFMA floor.)
// ---------------------------------------------------------------------------
__global__ __launch_bounds__(256) void proj_kernel(
    const float* __restrict__ x, const float* __restrict__ W,
    const float* __restrict__ bias)
{
    __shared__ float As[16][64];
    __shared__ float Bs[16][64];

    const int tid = threadIdx.x;
    const int m0 = blockIdx.y * 64;
    const int n0 = blockIdx.x * 64;
    const int tx = tid & 15;        // 0..15 -> 4 n-cols
    const int ty = tid >> 4;        // 0..15 -> 4 m-rows
    const int lr = tid >> 2;        // 0..63 row for staging
    const int lc = (tid & 3) * 4;   // 0/4/8/12 col for staging

    float acc[4][4];
#pragma unroll
    for (int i = 0; i < 4; i++)
#pragma unroll
        for (int j = 0; j < 4; j++) acc[i][j] = 0.f;

    for (int k0 = 0; k0 < EMBED; k0 += 16) {
        float4 av = *(const float4*)&x[(size_t)(m0 + lr) * EMBED + k0 + lc];
        float4 bv = make_float4(0.f, 0.f, 0.f, 0.f);
        if (n0 + lr < IN_PROJ)
            bv = *(const float4*)&W[(size_t)(n0 + lr) * EMBED + k0 + lc];
        As[lc + 0][lr] = av.x; As[lc + 1][lr] = av.y;
        As[lc + 2][lr] = av.z; As[lc + 3][lr] = av.w;
        Bs[lc + 0][lr] = bv.x; Bs[lc + 1][lr] = bv.y;
        Bs[lc + 2][lr] = bv.z; Bs[lc + 3][lr] = bv.w;
        __syncthreads();
#pragma unroll
        for (int k = 0; k < 16; k++) {
            float4 a = *(const float4*)&As[k][ty * 4];
            float4 b = *(const float4*)&Bs[k][tx * 4];
            float aa[4] = {a.x, a.y, a.z, a.w};
            float bb[4] = {b.x, b.y, b.z, b.w};
#pragma unroll
            for (int i = 0; i < 4; i++)
#pragma unroll
                for (int j = 0; j < 4; j++) acc[i][j] += aa[i] * bb[j];
        }
        __syncthreads();
    }

#pragma unroll
    for (int i = 0; i < 4; i++) {
        const int m = m0 + ty * 4 + i;
        const int s = m >> 3;      // row index in x is s*B + b
        const int bb = m & 7;
#pragma unroll
        for (int j = 0; j < 4; j++) {
            const int n = n0 + tx * 4 + j;
            if (n >= IN_PROJ) continue;
            const float v = acc[i][j] + bias[n];
            if (n < 256) {
                const int h = n >> 5, d = n & 31;
                g_Q[(((size_t)(bb * NH + h)) * SEQ + s) * QHD + d] = v;
            } else if (n < 512) {
                const int g = n - 256;
                const int h = g >> 5, d = g & 31;
                g_K[(((size_t)(bb * NH + h)) * SEQ + s) * QHD + d] = v;
            } else {
                const int g = n - 512;
                const int h = g >> 2, d = g & 3;
                g_P[(((size_t)(bb * NH + h)) * SEQ + s) * PD + d] = v;
            }
        }
    }
}

// ---------------------------------------------------------------------------
// Kernel 2: scores live in REGISTERS (64 per thread). CTA = (b, h, 16 t-rows).
// 256 threads: tg = tid>>7 picks 8 rows, cl = tid&127 picks s-lane.
// SMEM = K chunk (18KB) + Q/P/reduction scratch only -> 2 CTAs/SM.
// ---------------------------------------------------------------------------
#define TT 16
#define SC 128
#define KP 36    // K row pitch in floats: conflict-free for 8-lane LDS.128 phases
#define NCH (SEQ / SC)   // 8 chunks

__global__ __launch_bounds__(256, 2) void attn_kernel(
    const float* __restrict__ pos, const float* __restrict__ off,
    float* __restrict__ out)
{
    __shared__ float Ks[SC * KP];        // 18432 B
    __shared__ float Qs[TT * QHD];       // 2048 B
    __shared__ float4 Ps[TT];            // 256 B
    __shared__ float red[TT][4];         // 256 B

    const int tid = threadIdx.x;
    const int t0 = blockIdx.x * TT;
    const int h = blockIdx.y;
    const int b = blockIdx.z;

    const float* Qg = g_Q + ((size_t)(b * NH + h)) * SEQ * QHD;
    const float* Kg = g_K + ((size_t)(b * NH + h)) * SEQ * QHD;
    const float* Pg = g_P + ((size_t)(b * NH + h)) * SEQ * PD;

    // Stage Q tile (16x32) and P vectors once.
    if (tid < 128) {
        const int r = tid >> 3, d4 = tid & 7;
        *(float4*)&Qs[r * QHD + d4 * 4] =
            *(const float4*)&Qg[(size_t)(t0 + r) * QHD + d4 * 4];
    }
    if (tid < TT)
        Ps[tid] = *(const float4*)&Pg[(size_t)(t0 + tid) * PD];

    const int cl = tid & 127;    // s-lane within chunk
    const int tg = tid >> 7;     // 0..1 -> rows tg*8 .. tg*8+7
    const float* qrow = Qs + (tg * 8) * QHD;

    float sc_[8][NCH];           // registers: [row][chunk], s = c*SC + cl

#pragma unroll
    for (int c = 0; c < NCH; c++) {
        __syncthreads();         // K buffer reuse (and Q/P staging on c==0)
        // stage K chunk: 128 rows x 8 float4 over 256 threads -> 4 each
#pragma unroll
        for (int i = 0; i < 4; i++) {
            const int idx = tid + i * 256;
            const int s = idx >> 3, d4 = idx & 7;
            *(float4*)&Ks[s * KP + d4 * 4] =
                *(const float4*)&Kg[(size_t)(c * SC + s) * QHD + d4 * 4];
        }
        __syncthreads();

        float acc[8];
#pragma unroll
        for (int r = 0; r < 8; r++) acc[r] = 0.f;

#pragma unroll
        for (int d4 = 0; d4 < 8; d4++) {
            const float4 k4 = *(const float4*)&Ks[cl * KP + d4 * 4];
#pragma unroll
            for (int r = 0; r < 8; r++) {
                const float4 q4 = *(const float4*)&qrow[r * QHD + d4 * 4];
                acc[r] += q4.x * k4.x + q4.y * k4.y + q4.z * k4.z + q4.w * k4.w;
            }
        }

        // epilogue: + pos + offset into register scores
        const int s = c * SC + cl;
#pragma unroll
        for (int r = 0; r < 8; r++) {
            const int tglob = t0 + tg * 8 + r;
            const float4 pe = *(const float4*)&pos[((size_t)tglob * SEQ + s) * PD];
            const float o = off[((size_t)b * SEQ + tglob) * SEQ + s];
            const float4 p = Ps[tg * 8 + r];
            sc_[r][c] = acc[r] +
                p.x * pe.x + p.y * pe.y + p.z * pe.z + p.w * pe.w + o;
        }
    }

    // ------------------- softmax over s (128 lanes x 8 chunks) -------------
    const int lane = tid & 31;
    const int w4 = (tid >> 5) & 3;   // warp index within tg group (4 warps/row)

    // row max
    float m[8];
#pragma unroll
    for (int r = 0; r < 8; r++) {
        float v = sc_[r][0];
#pragma unroll
        for (int c = 1; c < NCH; c++) v = fmaxf(v, sc_[r][c]);
#pragma unroll
        for (int o_ = 16; o_ > 0; o_ >>= 1)
            v = fmaxf(v, __shfl_xor_sync(0xffffffffu, v, o_));
        m[r] = v;
    }
    __syncthreads();   // red[] free (after last K-stage consumers done)
    if (lane == 0) {
#pragma unroll
        for (int r = 0; r < 8; r++) red[tg * 8 + r][w4] = m[r];
    }
    __syncthreads();
#pragma unroll
    for (int r = 0; r < 8; r++) {
        const int row = tg * 8 + r;
        m[r] = fmaxf(fmaxf(red[row][0], red[row][1]),
                     fmaxf(red[row][2], red[row][3]));
    }
    __syncthreads();   // all max reads done before red reuse

    // exp + row sum
    float sum[8];
#pragma unroll
    for (int r = 0; r < 8; r++) {
        float s_ = 0.f;
#pragma unroll
        for (int c = 0; c < NCH; c++) {
            const float e = __expf(sc_[r][c] - m[r]);
            sc_[r][c] = e;
            s_ += e;
        }
#pragma unroll
        for (int o_ = 16; o_ > 0; o_ >>= 1)
            s_ += __shfl_xor_sync(0xffffffffu, s_, o_);
        sum[r] = s_;
    }
    if (lane == 0) {
#pragma unroll
        for (int r = 0; r < 8; r++) red[tg * 8 + r][w4] = sum[r];
    }
    __syncthreads();

    // normalize + store (coalesced: consecutive cl -> consecutive s)
#pragma unroll
    for (int r = 0; r < 8; r++) {
        const int row = tg * 8 + r;
        const float inv = 1.0f / (red[row][0] + red[row][1] +
                                  red[row][2] + red[row][3]);
        const int tglob = t0 + row;
        float* orow = &out[(((size_t)h * BSZ + b) * SEQ + tglob) * SEQ];
#pragma unroll
        for (int c = 0; c < NCH; c++)
            orow[c * SC + cl] = sc_[r][c] * inv;
    }
}

// ---------------------------------------------------------------------------
extern "C" void kernel_launch(void* const* d_in, const int* in_sizes, int n_in,
                              void* d_out, int out_size)
{
    const float* x    = (const float*)d_in[0];
    const float* pos  = (const float*)d_in[1];
    const float* off  = (const float*)d_in[2];
    const float* W    = (const float*)d_in[3];
    const float* bias = (const float*)d_in[4];
    float* out = (float*)d_out;

    dim3 gproj((IN_PROJ + 63) / 64, (SEQ * BSZ) / 64);   // 9 x 128
    proj_kernel<<<gproj, 256>>>(x, W, bias);

    dim3 gattn(SEQ / TT, NH, BSZ);                        // 64 x 8 x 8
    attn_kernel<<<gattn, 256>>>(pos, off, out);
}

// round 4
// speedup vs baseline: 5.8067x; 1.2084x over previous
#include <cuda_runtime.h>
#include <math_constants.h>

#define SEQ 1024
#define BSZ 8
#define EMBED 512
#define NH 8
#define QHD 32
#define PD 4
#define IN_PROJ 544

// Scratch for projected q/k/p, laid out [b][h][s][d] so kernel 2 streams contiguously.
__device__ float g_Q[BSZ * NH * SEQ * QHD];   // 8 MB
__device__ float g_K[BSZ * NH * SEQ * QHD];   // 8 MB
__device__ float g_P[BSZ * NH * SEQ * PD];    // 1 MB

// ---------------------------------------------------------------------------
// Kernel 1: xp = x @ W^T + b, scattered into g_Q / g_K / g_P.
// (Round-1 version, ~150us — at scalar FFMA floor.)
// ---------------------------------------------------------------------------
__global__ __launch_bounds__(256) void proj_kernel(
    const float* __restrict__ x, const float* __restrict__ W,
    const float* __restrict__ bias)
{
    __shared__ float As[16][64];
    __shared__ float Bs[16][64];

    const int tid = threadIdx.x;
    const int m0 = blockIdx.y * 64;
    const int n0 = blockIdx.x * 64;
    const int tx = tid & 15;
    const int ty = tid >> 4;
    const int lr = tid >> 2;
    const int lc = (tid & 3) * 4;

    float acc[4][4];
#pragma unroll
    for (int i = 0; i < 4; i++)
#pragma unroll
        for (int j = 0; j < 4; j++) acc[i][j] = 0.f;

    for (int k0 = 0; k0 < EMBED; k0 += 16) {
        float4 av = *(const float4*)&x[(size_t)(m0 + lr) * EMBED + k0 + lc];
        float4 bv = make_float4(0.f, 0.f, 0.f, 0.f);
        if (n0 + lr < IN_PROJ)
            bv = *(const float4*)&W[(size_t)(n0 + lr) * EMBED + k0 + lc];
        As[lc + 0][lr] = av.x; As[lc + 1][lr] = av.y;
        As[lc + 2][lr] = av.z; As[lc + 3][lr] = av.w;
        Bs[lc + 0][lr] = bv.x; Bs[lc + 1][lr] = bv.y;
        Bs[lc + 2][lr] = bv.z; Bs[lc + 3][lr] = bv.w;
        __syncthreads();
#pragma unroll
        for (int k = 0; k < 16; k++) {
            float4 a = *(const float4*)&As[k][ty * 4];
            float4 b = *(const float4*)&Bs[k][tx * 4];
            float aa[4] = {a.x, a.y, a.z, a.w};
            float bb[4] = {b.x, b.y, b.z, b.w};
#pragma unroll
            for (int i = 0; i < 4; i++)
#pragma unroll
                for (int j = 0; j < 4; j++) acc[i][j] += aa[i] * bb[j];
        }
        __syncthreads();
    }

#pragma unroll
    for (int i = 0; i < 4; i++) {
        const int m = m0 + ty * 4 + i;
        const int s = m >> 3;
        const int bb = m & 7;
#pragma unroll
        for (int j = 0; j < 4; j++) {
            const int n = n0 + tx * 4 + j;
            if (n >= IN_PROJ) continue;
            const float v = acc[i][j] + bias[n];
            if (n < 256) {
                const int h = n >> 5, d = n & 31;
                g_Q[(((size_t)(bb * NH + h)) * SEQ + s) * QHD + d] = v;
            } else if (n < 512) {
                const int g = n - 256;
                const int h = g >> 5, d = g & 31;
                g_K[(((size_t)(bb * NH + h)) * SEQ + s) * QHD + d] = v;
            } else {
                const int g = n - 512;
                const int h = g >> 2, d = g & 3;
                g_P[(((size_t)(bb * NH + h)) * SEQ + s) * PD + d] = v;
            }
        }
    }
}

// ---------------------------------------------------------------------------
// Kernel 2: scores in registers; thread tile = 4 t-rows x 8 s-values.
// CTA = (b, h, 16 t-rows). 256 threads: tg = tid>>6 -> 4 rows, cl = tid&63.
// SC=512 K chunk in SMEM (74KB), 2 chunks. 2 CTAs/SM.
// ---------------------------------------------------------------------------
#define TT 16
#define SC 512
#define KP 36    // K row pitch (floats): 8-lane LDS.128 phases conflict-free
#define NCH (SEQ / SC)   // 2

#define KS_FLOATS (SC * KP)                 // 18432
#define QS_OFF KS_FLOATS                    // Qs: TT*QHD = 512
#define PS_OFF (QS_OFF + TT * QHD)          // Ps: TT*4
#define RED_OFF (PS_OFF + TT * PD)          // red: TT*2
#define SM_FLOATS (RED_OFF + TT * 2)        // 19040 floats = 76160 B

__global__ __launch_bounds__(256, 2) void attn_kernel(
    const float* __restrict__ pos, const float* __restrict__ off,
    float* __restrict__ out)
{
    extern __shared__ float sm[];
    float* Ks = sm;
    float* Qs = sm + QS_OFF;
    float4* Ps = (float4*)(sm + PS_OFF);
    float* red = sm + RED_OFF;              // [TT][2]

    const int tid = threadIdx.x;
    const int t0 = blockIdx.x * TT;
    const int h = blockIdx.y;
    const int b = blockIdx.z;

    const float* Qg = g_Q + ((size_t)(b * NH + h)) * SEQ * QHD;
    const float* Kg = g_K + ((size_t)(b * NH + h)) * SEQ * QHD;
    const float* Pg = g_P + ((size_t)(b * NH + h)) * SEQ * PD;

    // Stage Q tile (16x32) and P vectors once.
    if (tid < 128) {
        const int r = tid >> 3, d4 = tid & 7;
        *(float4*)&Qs[r * QHD + d4 * 4] =
            *(const float4*)&Qg[(size_t)(t0 + r) * QHD + d4 * 4];
    }
    if (tid < TT)
        Ps[tid] = *(const float4*)&Pg[(size_t)(t0 + tid) * PD];

    const int cl = tid & 63;     // s-lane; s = c*SC + j*64 + cl
    const int tg = tid >> 6;     // 0..3 -> rows tg*4 .. tg*4+3
    const float* qrow = Qs + (tg * 4) * QHD;

    float sc_[4][NCH][8];        // [row][chunk][j]

#pragma unroll
    for (int c = 0; c < NCH; c++) {
        __syncthreads();         // K buffer reuse (and Q/P staging on c==0)
        // stage K chunk: 512 rows x 8 float4 over 256 threads -> 16 each
#pragma unroll
        for (int i = 0; i < (SC * 8) / 256; i++) {
            const int idx = tid + i * 256;
            const int s = idx >> 3, d4 = idx & 7;
            *(float4*)&Ks[s * KP + d4 * 4] =
                *(const float4*)&Kg[(size_t)(c * SC + s) * QHD + d4 * 4];
        }
        __syncthreads();

#pragma unroll
        for (int r = 0; r < 4; r++)
#pragma unroll
            for (int j = 0; j < 8; j++) sc_[r][c][j] = 0.f;

#pragma unroll
        for (int d4 = 0; d4 < 8; d4++) {
            float4 q4[4];
#pragma unroll
            for (int r = 0; r < 4; r++)
                q4[r] = *(const float4*)&qrow[r * QHD + d4 * 4];
#pragma unroll
            for (int j = 0; j < 8; j++) {
                const float4 k4 = *(const float4*)&Ks[(cl + j * 64) * KP + d4 * 4];
#pragma unroll
                for (int r = 0; r < 4; r++) {
                    sc_[r][c][j] += q4[r].x * k4.x + q4[r].y * k4.y +
                                    q4[r].z * k4.z + q4[r].w * k4.w;
                }
            }
        }

        // epilogue: + pos + offset
#pragma unroll
        for (int r = 0; r < 4; r++) {
            const int tglob = t0 + tg * 4 + r;
            const float4 p = Ps[tg * 4 + r];
#pragma unroll
            for (int j = 0; j < 8; j++) {
                const int s = c * SC + j * 64 + cl;
                const float4 pe = *(const float4*)&pos[((size_t)tglob * SEQ + s) * PD];
                const float o = off[((size_t)b * SEQ + tglob) * SEQ + s];
                sc_[r][c][j] += p.x * pe.x + p.y * pe.y + p.z * pe.z + p.w * pe.w + o;
            }
        }
    }

    // ------------------- softmax (row owned by 64 lanes = 2 warps) ---------
    const int lane = tid & 31;
    const int w2 = (tid >> 5) & 1;

    float m[4];
#pragma unroll
    for (int r = 0; r < 4; r++) {
        float v = -CUDART_INF_F;
#pragma unroll
        for (int c = 0; c < NCH; c++)
#pragma unroll
            for (int j = 0; j < 8; j++) v = fmaxf(v, sc_[r][c][j]);
#pragma unroll
        for (int o_ = 16; o_ > 0; o_ >>= 1)
            v = fmaxf(v, __shfl_xor_sync(0xffffffffu, v, o_));
        m[r] = v;
    }
    __syncthreads();
    if (lane == 0) {
#pragma unroll
        for (int r = 0; r < 4; r++) red[(tg * 4 + r) * 2 + w2] = m[r];
    }
    __syncthreads();
#pragma unroll
    for (int r = 0; r < 4; r++) {
        const int row = tg * 4 + r;
        m[r] = fmaxf(red[row * 2 + 0], red[row * 2 + 1]);
    }
    __syncthreads();

    float sum[4];
#pragma unroll
    for (int r = 0; r < 4; r++) {
        float s_ = 0.f;
#pragma unroll
        for (int c = 0; c < NCH; c++)
#pragma unroll
            for (int j = 0; j < 8; j++) {
                const float e = __expf(sc_[r][c][j] - m[r]);
                sc_[r][c][j] = e;
                s_ += e;
            }
#pragma unroll
        for (int o_ = 16; o_ > 0; o_ >>= 1)
            s_ += __shfl_xor_sync(0xffffffffu, s_, o_);
        sum[r] = s_;
    }
    if (lane == 0) {
#pragma unroll
        for (int r = 0; r < 4; r++) red[(tg * 4 + r) * 2 + w2] = sum[r];
    }
    __syncthreads();

#pragma unroll
    for (int r = 0; r < 4; r++) {
        const int row = tg * 4 + r;
        const float inv = 1.0f / (red[row * 2 + 0] + red[row * 2 + 1]);
        const int tglob = t0 + row;
        float* orow = &out[(((size_t)h * BSZ + b) * SEQ + tglob) * SEQ];
#pragma unroll
        for (int c = 0; c < NCH; c++)
#pragma unroll
            for (int j = 0; j < 8; j++)
                orow[c * SC + j * 64 + cl] = sc_[r][c][j] * inv;
    }
}

// ---------------------------------------------------------------------------
extern "C" void kernel_launch(void* const* d_in, const int* in_sizes, int n_in,
                              void* d_out, int out_size)
{
    const float* x    = (const float*)d_in[0];
    const float* pos  = (const float*)d_in[1];
    const float* off  = (const float*)d_in[2];
    const float* W    = (const float*)d_in[3];
    const float* bias = (const float*)d_in[4];
    float* out = (float*)d_out;

    cudaFuncSetAttribute(attn_kernel, cudaFuncAttributeMaxDynamicSharedMemorySize,
                         SM_FLOATS * (int)sizeof(float));

    dim3 gproj((IN_PROJ + 63) / 64, (SEQ * BSZ) / 64);   // 9 x 128
    proj_kernel<<<gproj, 256>>>(x, W, bias);

    dim3 gattn(SEQ / TT, NH, BSZ);                        // 64 x 8 x 8
    attn_kernel<<<gattn, 256, SM_FLOATS * (int)sizeof(float)>>>(pos, off, out);
}